// round 3
// baseline (speedup 1.0000x reference)
#include <cuda_runtime.h>
#include <cuda_bf16.h>
#include <math.h>

#define N_NODES 10000
#define N_EDGES 160000
#define N_TOT   (N_EDGES + N_NODES)
#define G       64
#define D_IN    1280
#define D_HID   512
#define D_OUT   256

// ---------------- scratch (static device globals; no allocation) ----------------
__device__ int   g_deg[N_NODES];
__device__ float g_dis[N_NODES];
__device__ int   g_rowptr[N_NODES + 1];
__device__ int   g_cursor[N_NODES];
__device__ int   g_col[N_TOT];
__device__ float g_val[N_TOT];
__device__ float g_h1[(size_t)N_NODES * D_HID];   // GEMM output (pre-aggregation)
__device__ float g_h2[(size_t)N_NODES * D_HID];   // aggregate output (next GEMM input)
__device__ float g_pool[G * D_OUT];
__device__ int   g_gcnt[G];
__device__ int   g_goff[G + 1];

// ---------------- graph preprocessing ----------------
__global__ void init_kernel() {
    int i = blockIdx.x * blockDim.x + threadIdx.x;
    if (i < N_NODES) g_deg[i] = 1;       // self loop
    if (i < G) g_gcnt[i] = 0;
}

__global__ void hist_kernel(const int* __restrict__ dst,
                            const int* __restrict__ batch) {
    int e = blockIdx.x * blockDim.x + threadIdx.x;
    if (e < N_EDGES) atomicAdd(&g_deg[dst[e]], 1);
    if (e < N_NODES) atomicAdd(&g_gcnt[batch[e]], 1);
}

__global__ void scan_kernel() {
    __shared__ int sdata[1024];
    int t = threadIdx.x;
    int carry = 0;
    for (int base = 0; base < N_NODES; base += 1024) {
        int i = base + t;
        int v = (i < N_NODES) ? g_deg[i] : 0;
        sdata[t] = v;
        __syncthreads();
        for (int off = 1; off < 1024; off <<= 1) {
            int tmp = (t >= off) ? sdata[t - off] : 0;
            __syncthreads();
            sdata[t] += tmp;
            __syncthreads();
        }
        if (i < N_NODES) {
            int excl = carry + sdata[t] - v;
            g_rowptr[i] = excl;
            g_cursor[i] = excl;
            g_dis[i] = rsqrtf((float)v);
        }
        carry += sdata[1023];
        __syncthreads();
    }
    if (t == 0) {
        g_rowptr[N_NODES] = carry;
        int acc = 0;
        for (int gg = 0; gg < G; gg++) { g_goff[gg] = acc; acc += g_gcnt[gg]; }
        g_goff[G] = acc;
    }
}

__global__ void fill_csr_kernel(const int* __restrict__ src,
                                const int* __restrict__ dst) {
    int e = blockIdx.x * blockDim.x + threadIdx.x;
    if (e >= N_TOT) return;
    int s, d;
    if (e < N_EDGES) { s = src[e]; d = dst[e]; }
    else             { s = d = e - N_EDGES; }
    int pos = atomicAdd(&g_cursor[d], 1);
    g_col[pos] = s;
    g_val[pos] = g_dis[s] * g_dis[d];
}

// ---------------- GEMM: g_h1[M,N] = A[M,K] @ B[K,N], fp32, 128x128x16 tile ----------
// A = Aext (layer 1 input x) if non-null, else g_h2 (previous layer output).
#define BM 128
#define BN 128
#define BK 16
__global__ __launch_bounds__(256) void gemm_kernel(const float* __restrict__ Aext,
                                                   const float* __restrict__ B,
                                                   int M, int K, int N) {
    const float* __restrict__ A = Aext ? Aext : g_h2;
    float* __restrict__ C = g_h1;
    __shared__ float As[BK][BM];   // transposed A tile
    __shared__ float Bs[BK][BN];
    int tid = threadIdx.x;
    int tx = tid & 15;       // 0..15  (col quads)
    int ty = tid >> 4;       // 0..15  (row quads)
    int block_row = blockIdx.y * BM;
    int block_col = blockIdx.x * BN;

    float acc[8][8];
#pragma unroll
    for (int i = 0; i < 8; i++)
#pragma unroll
        for (int j = 0; j < 8; j++) acc[i][j] = 0.f;

    for (int k0 = 0; k0 < K; k0 += BK) {
        // load A tile: 128 rows x 16 k = 512 float4; 2 per thread; store transposed
#pragma unroll
        for (int j = 0; j < 2; j++) {
            int v = tid * 2 + j;
            int r = v >> 2;
            int kc = (v & 3) * 4;
            int gr = block_row + r;
            float4 a = make_float4(0.f, 0.f, 0.f, 0.f);
            if (gr < M) a = *(const float4*)(A + (size_t)gr * K + k0 + kc);
            As[kc + 0][r] = a.x; As[kc + 1][r] = a.y;
            As[kc + 2][r] = a.z; As[kc + 3][r] = a.w;
        }
        // load B tile: 16 k-rows x 128 cols = 512 float4; 2 per thread
#pragma unroll
        for (int j = 0; j < 2; j++) {
            int v = tid * 2 + j;
            int kr = v >> 5;
            int c = (v & 31) * 4;
            *(float4*)&Bs[kr][c] = *(const float4*)(B + (size_t)(k0 + kr) * N + block_col + c);
        }
        __syncthreads();
#pragma unroll
        for (int k = 0; k < BK; k++) {
            float a[8], b[8];
            float4 a0 = *(float4*)&As[k][ty * 4];
            float4 a1 = *(float4*)&As[k][64 + ty * 4];
            float4 b0 = *(float4*)&Bs[k][tx * 4];
            float4 b1 = *(float4*)&Bs[k][64 + tx * 4];
            a[0]=a0.x; a[1]=a0.y; a[2]=a0.z; a[3]=a0.w;
            a[4]=a1.x; a[5]=a1.y; a[6]=a1.z; a[7]=a1.w;
            b[0]=b0.x; b[1]=b0.y; b[2]=b0.z; b[3]=b0.w;
            b[4]=b1.x; b[5]=b1.y; b[6]=b1.z; b[7]=b1.w;
#pragma unroll
            for (int i = 0; i < 8; i++)
#pragma unroll
                for (int j = 0; j < 8; j++) acc[i][j] += a[i] * b[j];
        }
        __syncthreads();
    }
    // store: rows {ty*4+i, 64+ty*4+i}, cols {tx*4.., 64+tx*4..}
#pragma unroll
    for (int ih = 0; ih < 2; ih++) {
#pragma unroll
        for (int i = 0; i < 4; i++) {
            int gr = block_row + ih * 64 + ty * 4 + i;
            if (gr >= M) continue;
            int ai = ih * 4 + i;
#pragma unroll
            for (int jh = 0; jh < 2; jh++) {
                float4 o = make_float4(acc[ai][jh*4+0], acc[ai][jh*4+1],
                                       acc[ai][jh*4+2], acc[ai][jh*4+3]);
                *(float4*)(C + (size_t)gr * N + block_col + jh * 64 + tx * 4) = o;
            }
        }
    }
}

// ---------------- aggregation: g_h2[i] = sum_{e in CSR(i)} val*g_h1[col] + bias ----
__global__ void aggregate_kernel(const float* __restrict__ bias,
                                 int D4, int do_relu) {
    int i = blockIdx.x;
    int t = threadIdx.x;     // < D4
    int s = g_rowptr[i], e = g_rowptr[i + 1];
    float4 acc = make_float4(0.f, 0.f, 0.f, 0.f);
    const float4* hin4 = (const float4*)g_h1;
    for (int p = s; p < e; p++) {
        int c = g_col[p];
        float v = g_val[p];
        float4 x = hin4[(size_t)c * D4 + t];
        acc.x += v * x.x; acc.y += v * x.y; acc.z += v * x.z; acc.w += v * x.w;
    }
    float4 b = ((const float4*)bias)[t];
    acc.x += b.x; acc.y += b.y; acc.z += b.z; acc.w += b.w;
    if (do_relu) {
        acc.x = fmaxf(acc.x, 0.f); acc.y = fmaxf(acc.y, 0.f);
        acc.z = fmaxf(acc.z, 0.f); acc.w = fmaxf(acc.w, 0.f);
    }
    ((float4*)g_h2)[(size_t)i * D4 + t] = acc;
}

// ---------------- pooling + L2 normalize (reads g_h2) ----------------
__global__ void pool_kernel() {
    __shared__ float red[256];
    int g = blockIdx.x, t = threadIdx.x;
    int s = g_goff[g], e = g_goff[g + 1];
    float acc = 0.f;
    for (int n = s; n < e; n++) acc += g_h2[(size_t)n * D_OUT + t];
    float cnt = (float)(e - s);
    float mean = acc / fmaxf(cnt, 1.f);
    red[t] = mean * mean;
    __syncthreads();
    for (int off = 128; off > 0; off >>= 1) {
        if (t < off) red[t] += red[t + off];
        __syncthreads();
    }
    float nrm = sqrtf(red[0]);
    g_pool[g * D_OUT + t] = mean / fmaxf(nrm, 1e-12f);
}

// ---------------- classifier MLP head ----------------
__global__ void mlp_kernel(const float* __restrict__ vec,
                           const float* __restrict__ cW1, const float* __restrict__ cb1,
                           const float* __restrict__ cW2, const float* __restrict__ cb2,
                           const float* __restrict__ cW3, const float* __restrict__ cb3,
                           float* __restrict__ out) {
    __shared__ float comb[512];
    __shared__ float z1[256];
    __shared__ float z2[64];
    int g = blockIdx.x, t = threadIdx.x;   // 256 threads
    comb[t] = g_pool[g * 256 + t];
    comb[256 + t] = vec[g * 256 + t];
    __syncthreads();
    float s1 = cb1[t];
    for (int k = 0; k < 512; k++) s1 += comb[k] * cW1[k * 256 + t];
    z1[t] = fmaxf(s1, 0.f);
    __syncthreads();
    if (t < 64) {
        float s2 = cb2[t];
        for (int k = 0; k < 256; k++) s2 += z1[k] * cW2[k * 64 + t];
        z2[t] = fmaxf(s2, 0.f);
    }
    __syncthreads();
    if (t == 0) {
        float s3 = cb3[0];
        for (int k = 0; k < 64; k++) s3 += z2[k] * cW3[k];
        out[g] = 1.f / (1.f + expf(-s3));
    }
}

// ---------------- launch ----------------
extern "C" void kernel_launch(void* const* d_in, const int* in_sizes, int n_in,
                              void* d_out, int out_size) {
    const float* x    = (const float*)d_in[0];
    const int*   ei   = (const int*)d_in[1];   // [2, E] int32 (JAX x64 disabled)
    const int*   bat  = (const int*)d_in[2];
    const float* vec  = (const float*)d_in[3];
    const float* W1 = (const float*)d_in[4],  *b1 = (const float*)d_in[5];
    const float* W2 = (const float*)d_in[6],  *b2 = (const float*)d_in[7];
    const float* W3 = (const float*)d_in[8],  *b3 = (const float*)d_in[9];
    const float* W4 = (const float*)d_in[10], *b4 = (const float*)d_in[11];
    const float* cW1 = (const float*)d_in[12], *cb1 = (const float*)d_in[13];
    const float* cW2 = (const float*)d_in[14], *cb2 = (const float*)d_in[15];
    const float* cW3 = (const float*)d_in[16], *cb3 = (const float*)d_in[17];
    float* out = (float*)d_out;

    const int* src = ei;
    const int* dst = ei + N_EDGES;

    // graph preprocessing
    init_kernel<<<(N_NODES + 255) / 256, 256>>>();
    hist_kernel<<<(N_EDGES + 255) / 256, 256>>>(dst, bat);
    scan_kernel<<<1, 1024>>>();
    fill_csr_kernel<<<(N_TOT + 255) / 256, 256>>>(src, dst);

    dim3 blk(256);
    // layer 1: x @ W1 -> g_h1 ; aggregate -> g_h2 (relu)
    gemm_kernel<<<dim3(D_HID / BN, (N_NODES + BM - 1) / BM), blk>>>(x, W1, N_NODES, D_IN, D_HID);
    aggregate_kernel<<<N_NODES, D_HID / 4>>>(b1, D_HID / 4, 1);
    // layer 2: g_h2 @ W2 -> g_h1 ; aggregate -> g_h2 (relu)
    gemm_kernel<<<dim3(D_HID / BN, (N_NODES + BM - 1) / BM), blk>>>(nullptr, W2, N_NODES, D_HID, D_HID);
    aggregate_kernel<<<N_NODES, D_HID / 4>>>(b2, D_HID / 4, 1);
    // layer 3
    gemm_kernel<<<dim3(D_HID / BN, (N_NODES + BM - 1) / BM), blk>>>(nullptr, W3, N_NODES, D_HID, D_HID);
    aggregate_kernel<<<N_NODES, D_HID / 4>>>(b3, D_HID / 4, 1);
    // layer 4 (no relu)
    gemm_kernel<<<dim3(D_OUT / BN, (N_NODES + BM - 1) / BM), blk>>>(nullptr, W4, N_NODES, D_HID, D_OUT);
    aggregate_kernel<<<N_NODES, D_OUT / 4>>>(b4, D_OUT / 4, 0);

    // pooling + normalize + head
    pool_kernel<<<G, 256>>>();
    mlp_kernel<<<G, 256>>>(vec, cW1, cb1, cW2, cb2, cW3, cb3, out);
}

// round 4
// speedup vs baseline: 1.6272x; 1.6272x over previous
#include <cuda_runtime.h>
#include <cuda_bf16.h>
#include <math.h>
#include <stdint.h>

#define N_NODES 10000
#define MPAD    10112           // 79 * 128 (padded row count, no M guards needed)
#define N_EDGES 160000
#define N_TOT   (N_EDGES + N_NODES)
#define G       64
#define D_IN    1280
#define D_HID   512
#define D_OUT   256

// ---------------- scratch (static device globals; no allocation) ----------------
__device__ int   g_deg[N_NODES];
__device__ float g_dis[N_NODES];
__device__ int   g_rowptr[N_NODES + 1];
__device__ int   g_cursor[N_NODES];
__device__ int   g_col[N_TOT];
__device__ float g_val[N_TOT];
__device__ float g_h1[(size_t)MPAD * D_HID];     // GEMM output (fp32, pre-aggregation)
__device__ float g_h2[(size_t)MPAD * D_HID];     // final-layer aggregate output (fp32)
__device__ __nv_bfloat16 g_xh[(size_t)MPAD * D_IN];   // x split hi
__device__ __nv_bfloat16 g_xl[(size_t)MPAD * D_IN];   // x split lo
__device__ __nv_bfloat16 g_ah[(size_t)MPAD * D_HID];  // activation split hi
__device__ __nv_bfloat16 g_al[(size_t)MPAD * D_HID];  // activation split lo
// weights, transposed [N][K], split hi/lo
__device__ __nv_bfloat16 g_w1h[D_IN * D_HID],  g_w1l[D_IN * D_HID];
__device__ __nv_bfloat16 g_w2h[D_HID * D_HID], g_w2l[D_HID * D_HID];
__device__ __nv_bfloat16 g_w3h[D_HID * D_HID], g_w3l[D_HID * D_HID];
__device__ __nv_bfloat16 g_w4h[D_HID * D_OUT], g_w4l[D_HID * D_OUT];
__device__ float g_pool[G * D_OUT];
__device__ int   g_gcnt[G];
__device__ int   g_goff[G + 1];

// ---------------- graph preprocessing ----------------
__global__ void init_kernel() {
    int i = blockIdx.x * blockDim.x + threadIdx.x;
    if (i < N_NODES) g_deg[i] = 1;       // self loop
    if (i < G) g_gcnt[i] = 0;
}

__global__ void hist_kernel(const int* __restrict__ dst,
                            const int* __restrict__ batch) {
    int e = blockIdx.x * blockDim.x + threadIdx.x;
    if (e < N_EDGES) atomicAdd(&g_deg[dst[e]], 1);
    if (e < N_NODES) atomicAdd(&g_gcnt[batch[e]], 1);
}

__global__ void scan_kernel() {
    __shared__ int sdata[1024];
    int t = threadIdx.x;
    int carry = 0;
    for (int base = 0; base < N_NODES; base += 1024) {
        int i = base + t;
        int v = (i < N_NODES) ? g_deg[i] : 0;
        sdata[t] = v;
        __syncthreads();
        for (int off = 1; off < 1024; off <<= 1) {
            int tmp = (t >= off) ? sdata[t - off] : 0;
            __syncthreads();
            sdata[t] += tmp;
            __syncthreads();
        }
        if (i < N_NODES) {
            int excl = carry + sdata[t] - v;
            g_rowptr[i] = excl;
            g_cursor[i] = excl;
            g_dis[i] = rsqrtf((float)v);
        }
        carry += sdata[1023];
        __syncthreads();
    }
    if (t == 0) {
        g_rowptr[N_NODES] = carry;
        int acc = 0;
        for (int gg = 0; gg < G; gg++) { g_goff[gg] = acc; acc += g_gcnt[gg]; }
        g_goff[G] = acc;
    }
}

__global__ void fill_csr_kernel(const int* __restrict__ src,
                                const int* __restrict__ dst) {
    int e = blockIdx.x * blockDim.x + threadIdx.x;
    if (e >= N_TOT) return;
    int s, d;
    if (e < N_EDGES) { s = src[e]; d = dst[e]; }
    else             { s = d = e - N_EDGES; }
    int pos = atomicAdd(&g_cursor[d], 1);
    g_col[pos] = s;
    g_val[pos] = g_dis[s] * g_dis[d];
}

// ---------------- bf16 split conversions ----------------
// weights: W[K][N] fp32 -> Wt_h/Wt_l[N][K] bf16 (transposed for B col-major mma)
__global__ void wconv_kernel(const float* __restrict__ W, int K, int N, int layer) {
    __nv_bfloat16 *Wh, *Wl;
    switch (layer) {
        case 1: Wh = g_w1h; Wl = g_w1l; break;
        case 2: Wh = g_w2h; Wl = g_w2l; break;
        case 3: Wh = g_w3h; Wl = g_w3l; break;
        default: Wh = g_w4h; Wl = g_w4l; break;
    }
    int idx = blockIdx.x * blockDim.x + threadIdx.x;
    if (idx >= K * N) return;
    int k = idx / N, n = idx - k * N;
    float v = W[idx];
    __nv_bfloat16 h = __float2bfloat16(v);
    __nv_bfloat16 l = __float2bfloat16(v - __bfloat162float(h));
    Wh[(size_t)n * K + k] = h;
    Wl[(size_t)n * K + k] = l;
}

// x[M][K] fp32 -> g_xh/g_xl bf16 (same layout)
__global__ void xconv_kernel(const float* __restrict__ x) {
    int idx = blockIdx.x * blockDim.x + threadIdx.x;
    if (idx >= N_NODES * D_IN) return;
    float v = x[idx];
    __nv_bfloat16 h = __float2bfloat16(v);
    g_xh[idx] = h;
    g_xl[idx] = __float2bfloat16(v - __bfloat162float(h));
}

// ---------------- tensor-core GEMM: g_h1[M,N] = A[M,K] @ Bt[N,K]^T ----------------
// A = (g_xh,g_xl) if asel==0 else (g_ah,g_al). 3-term bf16 split, fp32 accum.
// Block 128x128x32, 8 warps in 2(M) x 4(N), warp tile 64x32 = 4x4 m16n8 atoms.
#define GBK      32
#define ASTRIDE  40                  // bf16 per smem row (32 + 8 pad) -> 20 words, conflict-free
#define TILE_W   2560                // words per tile (128 * 20)
#define STAGE_W  10240               // words per stage (4 tiles)
#define SMEM_BYTES (2 * STAGE_W * 4) // 81920

__device__ __forceinline__ void cp16(uint32_t dst, const void* src) {
    asm volatile("cp.async.ca.shared.global [%0], [%1], 16;" :: "r"(dst), "l"(src));
}

__device__ __forceinline__ void mma_bf16(float c[4], const uint32_t a[4],
                                         uint32_t b0, uint32_t b1) {
    asm volatile(
        "mma.sync.aligned.m16n8k16.row.col.f32.bf16.bf16.f32 "
        "{%0,%1,%2,%3}, {%4,%5,%6,%7}, {%8,%9}, {%0,%1,%2,%3};"
        : "+f"(c[0]), "+f"(c[1]), "+f"(c[2]), "+f"(c[3])
        : "r"(a[0]), "r"(a[1]), "r"(a[2]), "r"(a[3]), "r"(b0), "r"(b1));
}

__global__ __launch_bounds__(256, 2) void mma_gemm_kernel(int asel, int layer,
                                                          int K, int N) {
    extern __shared__ __nv_bfloat16 smem[];
    const __nv_bfloat16 *Ah, *Al, *Bh, *Bl;
    if (asel == 0) { Ah = g_xh; Al = g_xl; } else { Ah = g_ah; Al = g_al; }
    switch (layer) {
        case 1: Bh = g_w1h; Bl = g_w1l; break;
        case 2: Bh = g_w2h; Bl = g_w2l; break;
        case 3: Bh = g_w3h; Bl = g_w3l; break;
        default: Bh = g_w4h; Bl = g_w4l; break;
    }
    int tid = threadIdx.x;
    int brow = blockIdx.y * 128;
    int bcol = blockIdx.x * 128;

    // cp.async thread mapping: 128 rows x 2 halves (16 bf16 each = 2x16B chunks)
    int lrow = tid >> 1;
    int lhalf = tid & 1;
    const __nv_bfloat16* agh = Ah + (size_t)(brow + lrow) * K + lhalf * 16;
    const __nv_bfloat16* agl = Al + (size_t)(brow + lrow) * K + lhalf * 16;
    const __nv_bfloat16* bgh = Bh + (size_t)(bcol + lrow) * K + lhalf * 16;
    const __nv_bfloat16* bgl = Bl + (size_t)(bcol + lrow) * K + lhalf * 16;
    uint32_t sbase = (uint32_t)__cvta_generic_to_shared(smem);
    uint32_t sdst = sbase + (uint32_t)(lrow * ASTRIDE + lhalf * 16) * 2;

    int warp = tid >> 5, lane = tid & 31;
    int wm = warp >> 2, wn = warp & 3;       // 2 x 4 warp grid
    int group = lane >> 2, quad = lane & 3;

    float acc[4][4][4];
#pragma unroll
    for (int i = 0; i < 4; i++)
#pragma unroll
        for (int j = 0; j < 4; j++)
#pragma unroll
            for (int v = 0; v < 4; v++) acc[i][j][v] = 0.f;

    int NK = K / GBK;
    // prologue: stage 0
    {
        const __nv_bfloat16* s4[4] = { agh, agl, bgh, bgl };
#pragma unroll
        for (int j = 0; j < 4; j++) {
            uint32_t d = sdst + j * (TILE_W * 4);
            cp16(d, s4[j]);
            cp16(d + 16, (const char*)s4[j] + 16);
        }
        asm volatile("cp.async.commit_group;");
    }

    for (int it = 0; it < NK; it++) {
        if (it + 1 < NK) {
            int k0 = (it + 1) * GBK;
            uint32_t stg = ((it + 1) & 1) * (STAGE_W * 4);
            const __nv_bfloat16* s4[4] = { agh + k0, agl + k0, bgh + k0, bgl + k0 };
#pragma unroll
            for (int j = 0; j < 4; j++) {
                uint32_t d = sdst + stg + j * (TILE_W * 4);
                cp16(d, s4[j]);
                cp16(d + 16, (const char*)s4[j] + 16);
            }
        }
        asm volatile("cp.async.commit_group;");
        asm volatile("cp.async.wait_group 1;");
        __syncthreads();

        const uint32_t* sw = (const uint32_t*)smem + (it & 1) * STAGE_W;
        const uint32_t* sAh32 = sw;
        const uint32_t* sAl32 = sw + TILE_W;
        const uint32_t* sBh32 = sw + 2 * TILE_W;
        const uint32_t* sBl32 = sw + 3 * TILE_W;

#pragma unroll
        for (int kk = 0; kk < 2; kk++) {
            int kb = kk * 8;
            uint32_t ah[4][4], al[4][4];
#pragma unroll
            for (int im = 0; im < 4; im++) {
                int r = wm * 64 + im * 16 + group;
                int i0 = r * 20 + kb + quad;
                int i1 = (r + 8) * 20 + kb + quad;
                ah[im][0] = sAh32[i0];     ah[im][1] = sAh32[i1];
                ah[im][2] = sAh32[i0 + 4]; ah[im][3] = sAh32[i1 + 4];
                al[im][0] = sAl32[i0];     al[im][1] = sAl32[i1];
                al[im][2] = sAl32[i0 + 4]; al[im][3] = sAl32[i1 + 4];
            }
#pragma unroll
            for (int in_ = 0; in_ < 4; in_++) {
                int n = wn * 32 + in_ * 8 + group;
                int j0 = n * 20 + kb + quad;
                uint32_t bh0 = sBh32[j0], bh1 = sBh32[j0 + 4];
                uint32_t bl0 = sBl32[j0], bl1 = sBl32[j0 + 4];
#pragma unroll
                for (int im = 0; im < 4; im++) {
                    mma_bf16(acc[im][in_], ah[im], bh0, bh1);
                    mma_bf16(acc[im][in_], ah[im], bl0, bl1);
                    mma_bf16(acc[im][in_], al[im], bh0, bh1);
                }
            }
        }
        __syncthreads();
    }

    // epilogue: store fp32 to g_h1 (rows padded, no guard)
#pragma unroll
    for (int im = 0; im < 4; im++) {
        int r = brow + wm * 64 + im * 16 + group;
#pragma unroll
        for (int in_ = 0; in_ < 4; in_++) {
            int c = bcol + wn * 32 + in_ * 8 + quad * 2;
            float2 lo = make_float2(acc[im][in_][0], acc[im][in_][1]);
            float2 hi = make_float2(acc[im][in_][2], acc[im][in_][3]);
            *(float2*)(g_h1 + (size_t)r * N + c) = lo;
            *(float2*)(g_h1 + (size_t)(r + 8) * N + c) = hi;
        }
    }
}

// ---------------- aggregation (layers 1-3): bias+relu, write bf16 hi/lo split ----
__global__ void aggregate_bf_kernel(const float* __restrict__ bias) {
    int i = blockIdx.x;
    int t = threadIdx.x;     // 128 threads (D_HID/4)
    int s = g_rowptr[i], e = g_rowptr[i + 1];
    float4 acc = make_float4(0.f, 0.f, 0.f, 0.f);
    const float4* hin4 = (const float4*)g_h1;
    for (int p = s; p < e; p++) {
        int c = g_col[p];
        float v = g_val[p];
        float4 x = hin4[(size_t)c * 128 + t];
        acc.x += v * x.x; acc.y += v * x.y; acc.z += v * x.z; acc.w += v * x.w;
    }
    float4 b = ((const float4*)bias)[t];
    acc.x = fmaxf(acc.x + b.x, 0.f); acc.y = fmaxf(acc.y + b.y, 0.f);
    acc.z = fmaxf(acc.z + b.z, 0.f); acc.w = fmaxf(acc.w + b.w, 0.f);
    __nv_bfloat16 hx = __float2bfloat16(acc.x), hy = __float2bfloat16(acc.y);
    __nv_bfloat16 hz = __float2bfloat16(acc.z), hw = __float2bfloat16(acc.w);
    __nv_bfloat16 lx = __float2bfloat16(acc.x - __bfloat162float(hx));
    __nv_bfloat16 ly = __float2bfloat16(acc.y - __bfloat162float(hy));
    __nv_bfloat16 lz = __float2bfloat16(acc.z - __bfloat162float(hz));
    __nv_bfloat16 lw = __float2bfloat16(acc.w - __bfloat162float(hw));
    __nv_bfloat162* oh = (__nv_bfloat162*)(g_ah + (size_t)i * D_HID);
    __nv_bfloat162* ol = (__nv_bfloat162*)(g_al + (size_t)i * D_HID);
    __nv_bfloat162 p0; p0.x = hx; p0.y = hy;
    __nv_bfloat162 p1; p1.x = hz; p1.y = hw;
    __nv_bfloat162 q0; q0.x = lx; q0.y = ly;
    __nv_bfloat162 q1; q1.x = lz; q1.y = lw;
    oh[t * 2] = p0; oh[t * 2 + 1] = p1;
    ol[t * 2] = q0; ol[t * 2 + 1] = q1;
}

// ---------------- aggregation (layer 4): bias, fp32 out, no relu ----------------
__global__ void aggregate_f32_kernel(const float* __restrict__ bias) {
    int i = blockIdx.x;
    int t = threadIdx.x;     // 64 threads (D_OUT/4)
    int s = g_rowptr[i], e = g_rowptr[i + 1];
    float4 acc = make_float4(0.f, 0.f, 0.f, 0.f);
    const float4* hin4 = (const float4*)g_h1;
    for (int p = s; p < e; p++) {
        int c = g_col[p];
        float v = g_val[p];
        float4 x = hin4[(size_t)c * 64 + t];
        acc.x += v * x.x; acc.y += v * x.y; acc.z += v * x.z; acc.w += v * x.w;
    }
    float4 b = ((const float4*)bias)[t];
    acc.x += b.x; acc.y += b.y; acc.z += b.z; acc.w += b.w;
    ((float4*)g_h2)[(size_t)i * 64 + t] = acc;
}

// ---------------- pooling + L2 normalize (reads g_h2) ----------------
__global__ void pool_kernel() {
    __shared__ float red[256];
    int g = blockIdx.x, t = threadIdx.x;
    int s = g_goff[g], e = g_goff[g + 1];
    float acc = 0.f;
    for (int n = s; n < e; n++) acc += g_h2[(size_t)n * D_OUT + t];
    float cnt = (float)(e - s);
    float mean = acc / fmaxf(cnt, 1.f);
    red[t] = mean * mean;
    __syncthreads();
    for (int off = 128; off > 0; off >>= 1) {
        if (t < off) red[t] += red[t + off];
        __syncthreads();
    }
    float nrm = sqrtf(red[0]);
    g_pool[g * D_OUT + t] = mean / fmaxf(nrm, 1e-12f);
}

// ---------------- classifier MLP head ----------------
__global__ void mlp_kernel(const float* __restrict__ vec,
                           const float* __restrict__ cW1, const float* __restrict__ cb1,
                           const float* __restrict__ cW2, const float* __restrict__ cb2,
                           const float* __restrict__ cW3, const float* __restrict__ cb3,
                           float* __restrict__ out) {
    __shared__ float comb[512];
    __shared__ float z1[256];
    __shared__ float z2[64];
    int g = blockIdx.x, t = threadIdx.x;   // 256 threads
    comb[t] = g_pool[g * 256 + t];
    comb[256 + t] = vec[g * 256 + t];
    __syncthreads();
    float s1 = cb1[t];
    for (int k = 0; k < 512; k++) s1 += comb[k] * cW1[k * 256 + t];
    z1[t] = fmaxf(s1, 0.f);
    __syncthreads();
    if (t < 64) {
        float s2 = cb2[t];
        for (int k = 0; k < 256; k++) s2 += z1[k] * cW2[k * 64 + t];
        z2[t] = fmaxf(s2, 0.f);
    }
    __syncthreads();
    if (t == 0) {
        float s3 = cb3[0];
        for (int k = 0; k < 64; k++) s3 += z2[k] * cW3[k];
        out[g] = 1.f / (1.f + expf(-s3));
    }
}

// ---------------- launch ----------------
extern "C" void kernel_launch(void* const* d_in, const int* in_sizes, int n_in,
                              void* d_out, int out_size) {
    const float* x    = (const float*)d_in[0];
    const int*   ei   = (const int*)d_in[1];   // [2, E] int32
    const int*   bat  = (const int*)d_in[2];
    const float* vec  = (const float*)d_in[3];
    const float* W1 = (const float*)d_in[4],  *b1 = (const float*)d_in[5];
    const float* W2 = (const float*)d_in[6],  *b2 = (const float*)d_in[7];
    const float* W3 = (const float*)d_in[8],  *b3 = (const float*)d_in[9];
    const float* W4 = (const float*)d_in[10], *b4 = (const float*)d_in[11];
    const float* cW1 = (const float*)d_in[12], *cb1 = (const float*)d_in[13];
    const float* cW2 = (const float*)d_in[14], *cb2 = (const float*)d_in[15];
    const float* cW3 = (const float*)d_in[16], *cb3 = (const float*)d_in[17];
    float* out = (float*)d_out;

    const int* src = ei;
    const int* dst = ei + N_EDGES;

    cudaFuncSetAttribute(mma_gemm_kernel,
                         cudaFuncAttributeMaxDynamicSharedMemorySize, SMEM_BYTES);

    // graph preprocessing
    init_kernel<<<(N_NODES + 255) / 256, 256>>>();
    hist_kernel<<<(N_EDGES + 255) / 256, 256>>>(dst, bat);
    scan_kernel<<<1, 1024>>>();
    fill_csr_kernel<<<(N_TOT + 255) / 256, 256>>>(src, dst);

    // conversions
    wconv_kernel<<<(D_IN * D_HID + 255) / 256, 256>>>(W1, D_IN, D_HID, 1);
    wconv_kernel<<<(D_HID * D_HID + 255) / 256, 256>>>(W2, D_HID, D_HID, 2);
    wconv_kernel<<<(D_HID * D_HID + 255) / 256, 256>>>(W3, D_HID, D_HID, 3);
    wconv_kernel<<<(D_HID * D_OUT + 255) / 256, 256>>>(W4, D_HID, D_OUT, 4);
    xconv_kernel<<<(N_NODES * D_IN + 255) / 256, 256>>>(x);

    dim3 blk(256);
    int gy = MPAD / 128;   // 79
    // layer 1
    mma_gemm_kernel<<<dim3(D_HID / 128, gy), blk, SMEM_BYTES>>>(0, 1, D_IN, D_HID);
    aggregate_bf_kernel<<<N_NODES, 128>>>(b1);
    // layer 2
    mma_gemm_kernel<<<dim3(D_HID / 128, gy), blk, SMEM_BYTES>>>(1, 2, D_HID, D_HID);
    aggregate_bf_kernel<<<N_NODES, 128>>>(b2);
    // layer 3
    mma_gemm_kernel<<<dim3(D_HID / 128, gy), blk, SMEM_BYTES>>>(1, 3, D_HID, D_HID);
    aggregate_bf_kernel<<<N_NODES, 128>>>(b3);
    // layer 4
    mma_gemm_kernel<<<dim3(D_OUT / 128, gy), blk, SMEM_BYTES>>>(1, 4, D_HID, D_OUT);
    aggregate_f32_kernel<<<N_NODES, 64>>>(b4);

    // pooling + normalize + head
    pool_kernel<<<G, 256>>>();
    mlp_kernel<<<G, 256>>>(vec, cW1, cb1, cW2, cb2, cW3, cb3, out);
}